// round 12
// baseline (speedup 1.0000x reference)
#include <cuda_runtime.h>

#define NB 16
#define CH 256
#define KS 6
#define MS 22
#define HO 17
#define OUT_PER_N (HO*HO)          // 289
#define TOT_OUT (NB*OUT_PER_N)     // 4624
#define CPB 16                     // channels per block
#define NCHUNK (CH/CPB)            // 16
#define RS 23                      // smem row stride
#define CSTR 507                   // channel tile stride
#define ZSTR 37                    // z tile stride
#define TPB 288                    // 16 cl * 9 pairs * 2 halves
#define OXW 9
#define XCOLS 14
#define IDX4 (TOT_OUT/4)           // 1156 float4 columns
#define NL 7                       // ceil(1936/288) front-batched loads/thread

// partials: [chunk][idx], 16B-aligned
__device__ float4 g_p4[NCHUNK * IDX4];
__device__ float4 g_mean4[IDX4];
__device__ int    g_count = 0;     // returns to 0 every launch

__device__ __forceinline__ float fsqrt_fast(float a) {
    float r; asm("sqrt.approx.f32 %0, %1;" : "=f"(r) : "f"(a)); return r;
}
__device__ __forceinline__ float4 ldcg4(const float4* p) {
    float4 v;
    asm volatile("ld.global.cg.v4.f32 {%0,%1,%2,%3}, [%4];"
                 : "=f"(v.x), "=f"(v.y), "=f"(v.z), "=f"(v.w) : "l"(p));
    return v;
}

// ---------------------------------------------------------------------------
// Kernel 1: per-(chunk, n) sliding correlation. (unchanged from R11)
// Load phase front-batches 7 LDG.128 per thread (MLP=7) before any STS.
// Compute: thread = (channel, oy-pair, ox-half): 2 rows x 9 cols, z in regs.
// ---------------------------------------------------------------------------
__global__ __launch_bounds__(TPB, 2) void corr_kernel(
    const float* __restrict__ z, const float* __restrict__ x,
    const float* __restrict__ w)
{
    __shared__ float xs[CPB * CSTR];      // 8112 floats; reused as reduce scratch
    __shared__ float zs[CPB * ZSTR];      // 592

    const int chunk = blockIdx.x;
    const int n     = blockIdx.y;
    const int t     = threadIdx.x;

    // --- phase A: front-batched gmem loads (7 independent LDG.128) ---
    const float4* xg4 = (const float4*)(x + (size_t)(n * CH + chunk * CPB) * (MS * MS));
    float4 v[NL];
#pragma unroll
    for (int i = 0; i < NL; i++) {
        int e4 = t + i * TPB;
        if (e4 < CPB * 121) v[i] = xg4[e4];
    }
    const float* zg = z + (size_t)(n * CH + chunk * CPB) * (KS * KS);
    float zv0 = 0.f, zv1 = 0.f;
    {
        int e0 = t, e1 = t + TPB;
        if (e0 < CPB * KS * KS) zv0 = zg[e0];
        if (e1 < CPB * KS * KS) zv1 = zg[e1];
    }

    // --- phase B: sqrt + smem stores ---
#pragma unroll
    for (int i = 0; i < NL; i++) {
        int e4 = t + i * TPB;
        if (e4 < CPB * 121) {
            unsigned cl   = (unsigned)e4 / 121u;
            unsigned rem4 = (unsigned)e4 - cl * 121u;
            unsigned r0   = (2u * rem4) / 11u;        // (4*rem4)/22
            unsigned c0   = 4u * rem4 - 22u * r0;     // even, 0..20
            unsigned base = cl * CSTR + r0 * RS + c0;
            unsigned p    = (c0 == 20u) ? 1u : 0u;    // wrap shifts exactly +1
            xs[base + 0]     = fsqrt_fast(v[i].x);
            xs[base + 1]     = fsqrt_fast(v[i].y);
            xs[base + 2 + p] = fsqrt_fast(v[i].z);
            xs[base + 3 + p] = fsqrt_fast(v[i].w);
        }
    }
    {
        int e0 = t, e1 = t + TPB;
        if (e0 < CPB * KS * KS) {
            unsigned cl = (unsigned)e0 / 36u, k = (unsigned)e0 - cl * 36u;
            zs[cl * ZSTR + k] = fsqrt_fast(zv0) * w[chunk * CPB + cl];
        }
        if (e1 < CPB * KS * KS) {
            unsigned cl = (unsigned)e1 / 36u, k = (unsigned)e1 - cl * 36u;
            zs[cl * ZSTR + k] = fsqrt_fast(zv1) * w[chunk * CPB + cl];
        }
    }
    __syncthreads();

    // --- compute: thread = (cl, pair, half) ---
    const int cl   = t & 15;
    const int ph   = t >> 4;              // 0..17
    const int pair = ph % 9;
    const int half = ph / 9;
    const int oy0  = pair * 2;            // 0..16 (pair 8: single row)
    const int ox0  = half * OXW;          // 0 or 9
    const float* xb = &xs[cl * CSTR + ox0];

    float zr[KS * KS];
#pragma unroll
    for (int i = 0; i < KS * KS; i++) zr[i] = zs[cl * ZSTR + i];

    float a0[OXW], a1[OXW];
#pragma unroll
    for (int i = 0; i < OXW; i++) { a0[i] = 0.f; a1[i] = 0.f; }

#pragma unroll
    for (int r = 0; r < 7; r++) {
        int row = oy0 + r;
        if (row > MS - 1) row = MS - 1;   // pair 8, r==6: dummy (feeds a1 only)
        float xr[XCOLS];
        // half==1, j==13 reads the pad slot: feeds only acc[8], discarded below.
#pragma unroll
        for (int j = 0; j < XCOLS; j++) xr[j] = xb[row * RS + j];
        if (r < 6) {
#pragma unroll
            for (int k2 = 0; k2 < KS; k2++) {
                float zv = zr[r * KS + k2];
#pragma unroll
                for (int i = 0; i < OXW; i++)
                    a0[i] = fmaf(xr[i + k2], zv, a0[i]);
            }
        }
        if (r >= 1) {
#pragma unroll
            for (int k2 = 0; k2 < KS; k2++) {
                float zv = zr[(r - 1) * KS + k2];
#pragma unroll
                for (int i = 0; i < OXW; i++)
                    a1[i] = fmaf(xr[i + k2], zv, a1[i]);
            }
        }
    }

    // --- block reduce over 16 channel lanes (fixed order -> deterministic) ---
    __syncthreads();
    float* scratch = xs;                  // 16 * 289 = 4624 floats
    const int nox = (half == 0) ? OXW : (OXW - 1);
#pragma unroll
    for (int i = 0; i < OXW; i++)
        if (i < nox) scratch[cl * OUT_PER_N + oy0 * HO + ox0 + i] = a0[i];
    if (pair < 8) {
#pragma unroll
        for (int i = 0; i < OXW; i++)
            if (i < nox) scratch[cl * OUT_PER_N + (oy0 + 1) * HO + ox0 + i] = a1[i];
    }
    __syncthreads();

    float* gp = (float*)g_p4;             // [chunk][4624]
    for (int idx = t; idx < OUT_PER_N; idx += TPB) {
        float s = 0.f;
#pragma unroll
        for (int c2 = 0; c2 < CPB; c2++) s += scratch[c2 * OUT_PER_N + idx];
        gp[chunk * TOT_OUT + n * OUT_PER_N + idx] = s;
    }
}

// ---------------------------------------------------------------------------
// Kernel 2 (fused): 3-block x 512-thread chunk reduce; last block does BN
// with a WIDE tail (512 threads, only 3 front-batched loads each).
// ---------------------------------------------------------------------------
#define CRB 512
#define CRG 3                             // 3*512 = 1536 >= 1156
#define VPT 3                             // 512*3 >= 1156 float4 columns
__global__ __launch_bounds__(CRB) void reduce_bn(
    float* __restrict__ out,
    const float* __restrict__ bw, const float* __restrict__ bb)
{
    const int t = threadIdx.x;
    const int idx4 = blockIdx.x * CRB + t;

    if (idx4 < IDX4) {
        float4 a0 = make_float4(0.f,0.f,0.f,0.f), a1 = a0, a2 = a0, a3 = a0;
#pragma unroll
        for (int ch = 0; ch < NCHUNK; ch += 4) {
            float4 p0 = g_p4[(ch + 0) * IDX4 + idx4];
            float4 p1 = g_p4[(ch + 1) * IDX4 + idx4];
            float4 p2 = g_p4[(ch + 2) * IDX4 + idx4];
            float4 p3 = g_p4[(ch + 3) * IDX4 + idx4];
            a0.x += p0.x; a0.y += p0.y; a0.z += p0.z; a0.w += p0.w;
            a1.x += p1.x; a1.y += p1.y; a1.z += p1.z; a1.w += p1.w;
            a2.x += p2.x; a2.y += p2.y; a2.z += p2.z; a2.w += p2.w;
            a3.x += p3.x; a3.y += p3.y; a3.z += p3.z; a3.w += p3.w;
        }
        float4 r;
        r.x = ((a0.x + a1.x) + (a2.x + a3.x)) * (1.f/36.f);
        r.y = ((a0.y + a1.y) + (a2.y + a3.y)) * (1.f/36.f);
        r.z = ((a0.z + a1.z) + (a2.z + a3.z)) * (1.f/36.f);
        r.w = ((a0.w + a1.w) + (a2.w + a3.w)) * (1.f/36.f);
        g_mean4[idx4] = r;
    }

    // --- last-block-done ticket ---
    __threadfence();
    __syncthreads();
    __shared__ bool amLast;
    if (t == 0) amLast = (atomicAdd(&g_count, 1) == CRG - 1);
    __syncthreads();
    if (!amLast) return;

    // --- BatchNorm over 4624 values: 512-thread tail, 3 loads each ---
    __shared__ float sred[CRB];
    __shared__ float s_mu, s_scale;

    float4 v[VPT];
#pragma unroll
    for (int g = 0; g < VPT; g++) {
        int i4 = t + g * CRB;
        v[g] = (i4 < IDX4) ? ldcg4(&g_mean4[i4]) : make_float4(0.f,0.f,0.f,0.f);
    }
    float lsum = 0.f;
#pragma unroll
    for (int g = 0; g < VPT; g++)
        lsum += (v[g].x + v[g].y) + (v[g].z + v[g].w);

    sred[t] = lsum; __syncthreads();
    for (int sz = CRB / 2; sz > 0; sz >>= 1) { if (t < sz) sred[t] += sred[t + sz]; __syncthreads(); }
    if (t == 0) s_mu = sred[0] / (float)TOT_OUT;
    __syncthreads();
    const float mu = s_mu;

    float lss = 0.f;
#pragma unroll
    for (int g = 0; g < VPT; g++) {
        int i4 = t + g * CRB;
        if (i4 < IDX4) {
            float dx = v[g].x - mu, dy = v[g].y - mu, dz = v[g].z - mu, dw = v[g].w - mu;
            lss += (dx*dx + dy*dy) + (dz*dz + dw*dw);
        }
    }
    sred[t] = lss; __syncthreads();
    for (int sz = CRB / 2; sz > 0; sz >>= 1) { if (t < sz) sred[t] += sred[t + sz]; __syncthreads(); }
    if (t == 0) s_scale = rsqrtf(sred[0] / (float)TOT_OUT + 1e-5f) * bw[0];
    __syncthreads();
    const float scale = s_scale;
    const float bias  = bb[0];

#pragma unroll
    for (int g = 0; g < VPT; g++) {
        int i4 = t + g * CRB;
        if (i4 < IDX4) {
            float4 o;
            o.x = (v[g].x - mu) * scale + bias;
            o.y = (v[g].y - mu) * scale + bias;
            o.z = (v[g].z - mu) * scale + bias;
            o.w = (v[g].w - mu) * scale + bias;
            ((float4*)out)[i4] = o;
        }
    }

    if (t == 0) g_count = 0;              // reset for next graph replay
}

extern "C" void kernel_launch(void* const* d_in, const int* in_sizes, int n_in,
                              void* d_out, int out_size)
{
    const float* z  = (const float*)d_in[0];
    const float* x  = (const float*)d_in[1];
    const float* w  = (const float*)d_in[2];
    const float* bw = (const float*)d_in[3];
    const float* bb = (const float*)d_in[4];

    int first_one = -1;
    for (int i = 0; i < n_in; i++) {
        if (in_sizes[i] == NB * CH * KS * KS)      z = (const float*)d_in[i];
        else if (in_sizes[i] == NB * CH * MS * MS) x = (const float*)d_in[i];
        else if (in_sizes[i] == CH)                w = (const float*)d_in[i];
        else if (in_sizes[i] == 1) {
            if (first_one < 0) { bw = (const float*)d_in[i]; first_one = i; }
            else                 bb = (const float*)d_in[i];
        }
    }

    dim3 grid(NCHUNK, NB);                       // 16 x 16 = 256 blocks
    corr_kernel<<<grid, TPB>>>(z, x, w);
    reduce_bn<<<CRG, CRB>>>((float*)d_out, bw, bb);
}

// round 13
// speedup vs baseline: 1.1358x; 1.1358x over previous
#include <cuda_runtime.h>

#define NB 16
#define CH 256
#define KS 6
#define MS 22
#define HO 17
#define OUT_PER_N (HO*HO)          // 289
#define TOT_OUT (NB*OUT_PER_N)     // 4624
#define CPB 16                     // channels per block
#define NCHUNK (CH/CPB)            // 16
#define RS 23                      // smem row stride
#define CSTR 507                   // channel tile stride
#define ZSTR 37                    // z tile stride
#define TPB 288                    // 16 cl * 9 pairs * 2 halves
#define OXW 9
#define XCOLS 14
#define IDX4 (TOT_OUT/4)           // 1156 float4 columns
#define NL 7                       // ceil(1936/288) front-batched loads/thread

// partials: [chunk][idx], 16B-aligned
__device__ float4 g_p4[NCHUNK * IDX4];
__device__ float4 g_mean4[IDX4];
__device__ int    g_count = 0;     // returns to 0 every launch

__device__ __forceinline__ float fsqrt_fast(float a) {
    float r; asm("sqrt.approx.f32 %0, %1;" : "=f"(r) : "f"(a)); return r;
}
__device__ __forceinline__ float4 ldcg4(const float4* p) {
    float4 v;
    asm volatile("ld.global.cg.v4.f32 {%0,%1,%2,%3}, [%4];"
                 : "=f"(v.x), "=f"(v.y), "=f"(v.z), "=f"(v.w) : "l"(p));
    return v;
}

// ---------------------------------------------------------------------------
// Kernel 1: per-(chunk, n) sliding correlation. (unchanged from R11 winner)
// ---------------------------------------------------------------------------
__global__ __launch_bounds__(TPB, 2) void corr_kernel(
    const float* __restrict__ z, const float* __restrict__ x,
    const float* __restrict__ w)
{
    __shared__ float xs[CPB * CSTR];      // 8112 floats; reused as reduce scratch
    __shared__ float zs[CPB * ZSTR];      // 592

    const int chunk = blockIdx.x;
    const int n     = blockIdx.y;
    const int t     = threadIdx.x;

    // --- phase A: front-batched gmem loads (7 independent LDG.128) ---
    const float4* xg4 = (const float4*)(x + (size_t)(n * CH + chunk * CPB) * (MS * MS));
    float4 v[NL];
#pragma unroll
    for (int i = 0; i < NL; i++) {
        int e4 = t + i * TPB;
        if (e4 < CPB * 121) v[i] = xg4[e4];
    }
    const float* zg = z + (size_t)(n * CH + chunk * CPB) * (KS * KS);
    float zv0 = 0.f, zv1 = 0.f;
    {
        int e0 = t, e1 = t + TPB;
        if (e0 < CPB * KS * KS) zv0 = zg[e0];
        if (e1 < CPB * KS * KS) zv1 = zg[e1];
    }

    // --- phase B: sqrt + smem stores ---
#pragma unroll
    for (int i = 0; i < NL; i++) {
        int e4 = t + i * TPB;
        if (e4 < CPB * 121) {
            unsigned cl   = (unsigned)e4 / 121u;
            unsigned rem4 = (unsigned)e4 - cl * 121u;
            unsigned r0   = (2u * rem4) / 11u;        // (4*rem4)/22
            unsigned c0   = 4u * rem4 - 22u * r0;     // even, 0..20
            unsigned base = cl * CSTR + r0 * RS + c0;
            unsigned p    = (c0 == 20u) ? 1u : 0u;    // wrap shifts exactly +1
            xs[base + 0]     = fsqrt_fast(v[i].x);
            xs[base + 1]     = fsqrt_fast(v[i].y);
            xs[base + 2 + p] = fsqrt_fast(v[i].z);
            xs[base + 3 + p] = fsqrt_fast(v[i].w);
        }
    }
    {
        int e0 = t, e1 = t + TPB;
        if (e0 < CPB * KS * KS) {
            unsigned cl = (unsigned)e0 / 36u, k = (unsigned)e0 - cl * 36u;
            zs[cl * ZSTR + k] = fsqrt_fast(zv0) * w[chunk * CPB + cl];
        }
        if (e1 < CPB * KS * KS) {
            unsigned cl = (unsigned)e1 / 36u, k = (unsigned)e1 - cl * 36u;
            zs[cl * ZSTR + k] = fsqrt_fast(zv1) * w[chunk * CPB + cl];
        }
    }
    __syncthreads();

    // --- compute: thread = (cl, pair, half) ---
    const int cl   = t & 15;
    const int ph   = t >> 4;              // 0..17
    const int pair = ph % 9;
    const int half = ph / 9;
    const int oy0  = pair * 2;            // 0..16 (pair 8: single row)
    const int ox0  = half * OXW;          // 0 or 9
    const float* xb = &xs[cl * CSTR + ox0];

    float zr[KS * KS];
#pragma unroll
    for (int i = 0; i < KS * KS; i++) zr[i] = zs[cl * ZSTR + i];

    float a0[OXW], a1[OXW];
#pragma unroll
    for (int i = 0; i < OXW; i++) { a0[i] = 0.f; a1[i] = 0.f; }

#pragma unroll
    for (int r = 0; r < 7; r++) {
        int row = oy0 + r;
        if (row > MS - 1) row = MS - 1;   // pair 8, r==6: dummy (feeds a1 only)
        float xr[XCOLS];
        // half==1, j==13 reads the pad slot: feeds only acc[8], discarded below.
#pragma unroll
        for (int j = 0; j < XCOLS; j++) xr[j] = xb[row * RS + j];
        if (r < 6) {
#pragma unroll
            for (int k2 = 0; k2 < KS; k2++) {
                float zv = zr[r * KS + k2];
#pragma unroll
                for (int i = 0; i < OXW; i++)
                    a0[i] = fmaf(xr[i + k2], zv, a0[i]);
            }
        }
        if (r >= 1) {
#pragma unroll
            for (int k2 = 0; k2 < KS; k2++) {
                float zv = zr[(r - 1) * KS + k2];
#pragma unroll
                for (int i = 0; i < OXW; i++)
                    a1[i] = fmaf(xr[i + k2], zv, a1[i]);
            }
        }
    }

    // --- block reduce over 16 channel lanes (fixed order -> deterministic) ---
    __syncthreads();
    float* scratch = xs;                  // 16 * 289 = 4624 floats
    const int nox = (half == 0) ? OXW : (OXW - 1);
#pragma unroll
    for (int i = 0; i < OXW; i++)
        if (i < nox) scratch[cl * OUT_PER_N + oy0 * HO + ox0 + i] = a0[i];
    if (pair < 8) {
#pragma unroll
        for (int i = 0; i < OXW; i++)
            if (i < nox) scratch[cl * OUT_PER_N + (oy0 + 1) * HO + ox0 + i] = a1[i];
    }
    __syncthreads();

    float* gp = (float*)g_p4;             // [chunk][4624]
    for (int idx = t; idx < OUT_PER_N; idx += TPB) {
        float s = 0.f;
#pragma unroll
        for (int c2 = 0; c2 < CPB; c2++) s += scratch[c2 * OUT_PER_N + idx];
        gp[chunk * TOT_OUT + n * OUT_PER_N + idx] = s;
    }
}

// ---------------------------------------------------------------------------
// Kernel 2 (fused): chunk reduce with ONE gmem load per thread.
// block = (16 chunks x 32 columns); smem tree over chunk dim (fixed order).
// 37 blocks; last block (ticket) runs the 512-thread BatchNorm tail.
// ---------------------------------------------------------------------------
#define RBT 512
#define RBCOLS 32
#define RBG ((IDX4 + RBCOLS - 1) / RBCOLS)     // 37 blocks
#define VPT 3                                  // tail: 512*3 >= 1156
__global__ __launch_bounds__(RBT) void reduce_bn(
    float* __restrict__ out,
    const float* __restrict__ bw, const float* __restrict__ bb)
{
    __shared__ float4 sp[NCHUNK][RBCOLS];      // 8 KB; reused by tail
    const int t     = threadIdx.x;
    const int chunk = t >> 5;                  // 0..15
    const int lane  = t & 31;
    const int idx4  = blockIdx.x * RBCOLS + lane;

    // one coalesced LDG.128 per thread
    float4 p = make_float4(0.f, 0.f, 0.f, 0.f);
    if (idx4 < IDX4) p = g_p4[chunk * IDX4 + idx4];
    sp[chunk][lane] = p;
    __syncthreads();

    // tree over chunk dim: 4 levels, deterministic
#pragma unroll
    for (int s = NCHUNK / 2; s >= 1; s >>= 1) {
        if (chunk < s) {
            float4 a = sp[chunk][lane];
            float4 b = sp[chunk + s][lane];
            a.x += b.x; a.y += b.y; a.z += b.z; a.w += b.w;
            sp[chunk][lane] = a;
        }
        __syncthreads();
    }
    if (chunk == 0 && idx4 < IDX4) {
        float4 a = sp[0][lane];
        a.x *= (1.f/36.f); a.y *= (1.f/36.f); a.z *= (1.f/36.f); a.w *= (1.f/36.f);
        g_mean4[idx4] = a;
    }

    // --- last-block-done ticket ---
    __threadfence();
    __syncthreads();
    __shared__ bool amLast;
    if (t == 0) amLast = (atomicAdd(&g_count, 1) == RBG - 1);
    __syncthreads();
    if (!amLast) return;

    // --- BatchNorm tail: 512 threads, 3 front-batched loads each ---
    float* sred = (float*)sp;                  // reuse smem
    __shared__ float s_mu, s_scale;

    float4 v[VPT];
#pragma unroll
    for (int g = 0; g < VPT; g++) {
        int i4 = t + g * RBT;
        v[g] = (i4 < IDX4) ? ldcg4(&g_mean4[i4]) : make_float4(0.f,0.f,0.f,0.f);
    }
    float lsum = 0.f;
#pragma unroll
    for (int g = 0; g < VPT; g++)
        lsum += (v[g].x + v[g].y) + (v[g].z + v[g].w);

    sred[t] = lsum; __syncthreads();
    for (int sz = RBT / 2; sz > 0; sz >>= 1) { if (t < sz) sred[t] += sred[t + sz]; __syncthreads(); }
    if (t == 0) s_mu = sred[0] / (float)TOT_OUT;
    __syncthreads();
    const float mu = s_mu;

    float lss = 0.f;
#pragma unroll
    for (int g = 0; g < VPT; g++) {
        int i4 = t + g * RBT;
        if (i4 < IDX4) {
            float dx = v[g].x - mu, dy = v[g].y - mu, dz = v[g].z - mu, dw = v[g].w - mu;
            lss += (dx*dx + dy*dy) + (dz*dz + dw*dw);
        }
    }
    sred[t] = lss; __syncthreads();
    for (int sz = RBT / 2; sz > 0; sz >>= 1) { if (t < sz) sred[t] += sred[t + sz]; __syncthreads(); }
    if (t == 0) s_scale = rsqrtf(sred[0] / (float)TOT_OUT + 1e-5f) * bw[0];
    __syncthreads();
    const float scale = s_scale;
    const float bias  = bb[0];

#pragma unroll
    for (int g = 0; g < VPT; g++) {
        int i4 = t + g * RBT;
        if (i4 < IDX4) {
            float4 o;
            o.x = (v[g].x - mu) * scale + bias;
            o.y = (v[g].y - mu) * scale + bias;
            o.z = (v[g].z - mu) * scale + bias;
            o.w = (v[g].w - mu) * scale + bias;
            ((float4*)out)[i4] = o;
        }
    }

    if (t == 0) g_count = 0;              // reset for next graph replay
}

extern "C" void kernel_launch(void* const* d_in, const int* in_sizes, int n_in,
                              void* d_out, int out_size)
{
    const float* z  = (const float*)d_in[0];
    const float* x  = (const float*)d_in[1];
    const float* w  = (const float*)d_in[2];
    const float* bw = (const float*)d_in[3];
    const float* bb = (const float*)d_in[4];

    int first_one = -1;
    for (int i = 0; i < n_in; i++) {
        if (in_sizes[i] == NB * CH * KS * KS)      z = (const float*)d_in[i];
        else if (in_sizes[i] == NB * CH * MS * MS) x = (const float*)d_in[i];
        else if (in_sizes[i] == CH)                w = (const float*)d_in[i];
        else if (in_sizes[i] == 1) {
            if (first_one < 0) { bw = (const float*)d_in[i]; first_one = i; }
            else                 bb = (const float*)d_in[i];
        }
    }

    dim3 grid(NCHUNK, NB);                       // 16 x 16 = 256 blocks
    corr_kernel<<<grid, TPB>>>(z, x, w);
    reduce_bn<<<RBG, RBT>>>((float*)d_out, bw, bb);
}